// round 1
// baseline (speedup 1.0000x reference)
#include <cuda_runtime.h>
#include <cuda_bf16.h>
#include <cstdint>

#define D_MODEL 256
#define NB 16
#define ACT_OFF 10
#define LN_EPS 1e-5f
#define WARPS_PER_BLOCK 8
#define THREADS (WARPS_PER_BLOCK * 32)

__global__ __launch_bounds__(THREADS)
void action_embedding_kernel(
    const int*   __restrict__ token_ids,     // [N]
    const int*   __restrict__ action_actors, // [N]
    const int*   __restrict__ action_streets,// [N]
    const float* __restrict__ legal_masks,   // [N, 16]
    const float* __restrict__ actor_emb,     // [2, 256]
    const float* __restrict__ street_emb,    // [4, 256]
    const float* __restrict__ type_emb,      // [16, 256]
    const float* __restrict__ mlp_w,         // [16, 256]
    const float* __restrict__ mlp_b,         // [256]
    const float* __restrict__ ln_gamma,      // [256]
    const float* __restrict__ ln_beta,       // [256]
    float*       __restrict__ out,           // [N, 256]
    int n_tok)
{
    __shared__ float Wsh[NB * D_MODEL];  // 16 KB

    // Cooperative stage of W into shared (vectorized)
    {
        const float4* src = reinterpret_cast<const float4*>(mlp_w);
        float4*       dst = reinterpret_cast<float4*>(Wsh);
        #pragma unroll
        for (int i = threadIdx.x; i < NB * D_MODEL / 4; i += THREADS)
            dst[i] = src[i];
    }
    __syncthreads();

    const int warp = threadIdx.x >> 5;
    const int lane = threadIdx.x & 31;
    const int t = blockIdx.x * WARPS_PER_BLOCK + warp;
    if (t >= n_tok) return;

    float4* out4 = reinterpret_cast<float4*>(out + (size_t)t * D_MODEL);

    const int tk = __ldg(token_ids + t);
    const bool active = (tk >= ACT_OFF) && (tk < ACT_OFF + NB);
    if (!active) {
        const float4 z = make_float4(0.f, 0.f, 0.f, 0.f);
        out4[lane]      = z;
        out4[lane + 32] = z;
        return;
    }

    int a   = __ldg(action_actors + t);  a = a < 0 ? 0 : (a > 1 ? 1 : a);
    int s   = __ldg(action_streets + t); s = s < 0 ? 0 : (s > 3 ? 3 : s);
    int aid = tk - ACT_OFF;              // already in [0,15] when active

    // Broadcast-load the 16 mask weights (all lanes same addresses -> L1 broadcast)
    float m[NB];
    {
        const float4* lm4 = reinterpret_cast<const float4*>(legal_masks + (size_t)t * NB);
        #pragma unroll
        for (int i = 0; i < 4; i++) {
            float4 v = __ldg(lm4 + i);
            m[4*i+0] = v.x; m[4*i+1] = v.y; m[4*i+2] = v.z; m[4*i+3] = v.w;
        }
    }

    // h[d] for d = 4*lane + c*128 + {0..3}
    float h[8];
    #pragma unroll
    for (int c = 0; c < 2; c++) {
        const int d0 = c * 128 + 4 * lane;
        float4 acc = __ldg(reinterpret_cast<const float4*>(mlp_b + d0));
        #pragma unroll
        for (int k = 0; k < NB; k++) {
            float4 w = *reinterpret_cast<const float4*>(&Wsh[k * D_MODEL + d0]);
            acc.x = fmaf(m[k], w.x, acc.x);
            acc.y = fmaf(m[k], w.y, acc.y);
            acc.z = fmaf(m[k], w.z, acc.z);
            acc.w = fmaf(m[k], w.w, acc.w);
        }
        h[4*c+0] = acc.x; h[4*c+1] = acc.y; h[4*c+2] = acc.z; h[4*c+3] = acc.w;
    }

    // Warp-level LayerNorm stats (sum, sumsq over 256 = 8 per lane x 32 lanes)
    float sum = 0.f, sq = 0.f;
    #pragma unroll
    for (int i = 0; i < 8; i++) { sum += h[i]; sq = fmaf(h[i], h[i], sq); }
    #pragma unroll
    for (int o = 16; o > 0; o >>= 1) {
        sum += __shfl_xor_sync(0xFFFFFFFFu, sum, o);
        sq  += __shfl_xor_sync(0xFFFFFFFFu, sq,  o);
    }
    const float inv_d = 1.0f / 256.0f;
    const float mu  = sum * inv_d;
    const float var = fmaf(sq, inv_d, -mu * mu);
    const float rs  = rsqrtf(var + LN_EPS);

    // Normalize + affine + ReLU + embedding sums, write out
    #pragma unroll
    for (int c = 0; c < 2; c++) {
        const int d0 = c * 128 + 4 * lane;
        float4 ga = __ldg(reinterpret_cast<const float4*>(ln_gamma + d0));
        float4 bb = __ldg(reinterpret_cast<const float4*>(ln_beta  + d0));
        float4 ea = __ldg(reinterpret_cast<const float4*>(actor_emb  + a   * D_MODEL + d0));
        float4 es = __ldg(reinterpret_cast<const float4*>(street_emb + s   * D_MODEL + d0));
        float4 et = __ldg(reinterpret_cast<const float4*>(type_emb   + aid * D_MODEL + d0));
        float4 r;
        r.x = fmaxf(fmaf((h[4*c+0] - mu) * rs, ga.x, bb.x), 0.f) + ea.x + es.x + et.x;
        r.y = fmaxf(fmaf((h[4*c+1] - mu) * rs, ga.y, bb.y), 0.f) + ea.y + es.y + et.y;
        r.z = fmaxf(fmaf((h[4*c+2] - mu) * rs, ga.z, bb.z), 0.f) + ea.z + es.z + et.z;
        r.w = fmaxf(fmaf((h[4*c+3] - mu) * rs, ga.w, bb.w), 0.f) + ea.w + es.w + et.w;
        out4[lane + c * 32] = r;
    }
}

extern "C" void kernel_launch(void* const* d_in, const int* in_sizes, int n_in,
                              void* d_out, int out_size)
{
    const int*   token_ids   = (const int*)  d_in[0];
    const int*   actors      = (const int*)  d_in[1];
    const int*   streets     = (const int*)  d_in[2];
    const float* legal_masks = (const float*)d_in[3];
    const float* actor_emb   = (const float*)d_in[4];
    const float* street_emb  = (const float*)d_in[5];
    const float* type_emb    = (const float*)d_in[6];
    const float* mlp_w       = (const float*)d_in[7];
    const float* mlp_b       = (const float*)d_in[8];
    const float* ln_gamma    = (const float*)d_in[9];
    const float* ln_beta     = (const float*)d_in[10];
    float* out = (float*)d_out;

    const int n_tok = in_sizes[0];  // B*S = 131072
    const int blocks = (n_tok + WARPS_PER_BLOCK - 1) / WARPS_PER_BLOCK;
    action_embedding_kernel<<<blocks, THREADS>>>(
        token_ids, actors, streets, legal_masks,
        actor_emb, street_emb, type_emb,
        mlp_w, mlp_b, ln_gamma, ln_beta,
        out, n_tok);
}